// round 10
// baseline (speedup 1.0000x reference)
#include <cuda_runtime.h>
#include <math.h>

#define Nn 128
#define Cc 256
#define Aa 512
#define NB 128
#define NT 512
#define KSPLIT 8
#define TS 66              // smem row stride (floats): even (8B-aligned rows)

// Scratch (device globals — no allocations allowed). Counters are used once
// per run and reset by their last arriver; cross-run visibility is guaranteed
// by the kernel launch boundary. g_genA is monotonic (compared, never reset).
__device__ float g_part[KSPLIT * 2 * Nn * Cc]; // K-split partials of [G;H]
__device__ float g_loss[Nn];
__device__ unsigned int g_l1A[16 * 32];        // tree barrier level-1 (128B apart)
__device__ unsigned int g_l2A;
__device__ unsigned int g_genA;
__device__ unsigned int g_l1B[16 * 32];        // completion tree
__device__ unsigned int g_l2B;

struct SmemG { float Xs[64][TS]; float Ws[64][TS]; };
struct SmemB {
    int mlist[Nn], tlist[Nn];
    float pk[Nn];
    float pG[Cc], pS1[Cc], pS2[Cc], pH[Cc];   // half-1 partial sums
    float red[8];
    float yk;
    int wM[4], wT[4];
};
union __align__(16) SmemU { SmemG g; SmemB b; };

// Sum the 8 K-split partials for element [row, col] of [G;H].
__device__ __forceinline__ float sum8(int row, int col) {
    float v = 0.f;
#pragma unroll
    for (int q = 0; q < KSPLIT; ++q)
        v += g_part[q * (2 * Nn * Cc) + row * Cc + col];
    return v;
}

__global__ __launch_bounds__(NT, 1)
void isda_fused_kernel(const float* __restrict__ W,
                       const float* __restrict__ bias,
                       const float* __restrict__ s,
                       const float* __restrict__ t,
                       const int* __restrict__ ts,
                       const int* __restrict__ tt,
                       float* __restrict__ out)
{
    __shared__ SmemU sm;
    __shared__ int sh_k;
    __shared__ int sh_last;
    const int tid  = threadIdx.x;
    const int bid  = blockIdx.x;
    const int lane = tid & 31;
    const int warp = tid >> 5;

    // GEMM tile coordinates: 16 output tiles (64x64) x 8-way K-split
    const int mt = bid & 3;
    const int ct = (bid >> 2) & 3;
    const int kt = bid >> 4;
    const int m0 = mt * 64, c0 = ct * 64, kb = kt * 64;

    // ---- Cycle-0 loads: raw inputs, no dependencies ----
    const float* xbase = (mt < 2) ? (s + (size_t)m0 * Aa)
                                  : (t + (size_t)(m0 - 128) * Aa);
    int my_ts = 0, my_tt = 0;
    if (tid < Nn) { my_ts = ts[tid]; my_tt = tt[tid]; }
    // Full tile staging: 64 rows x 16 float4 per array = 1024 float4;
    // 512 threads x 2 iterations. (R8 bug: only 8 float4/row were loaded.)
#pragma unroll
    for (int i = 0; i < 2; ++i) {
        const int idx = tid + i * 512;            // 0..1023
        const int r = idx >> 4, kq = idx & 15;    // kq*4 covers 0..60
        const float4 xv4 = *(const float4*)&xbase[(size_t)r * Aa + kb + kq * 4];
        const float4 wv4 = *(const float4*)&W[(size_t)(c0 + r) * Aa + kb + kq * 4];
        *(float2*)&sm.g.Xs[r][kq * 4]     = make_float2(xv4.x, xv4.y);
        *(float2*)&sm.g.Xs[r][kq * 4 + 2] = make_float2(xv4.z, xv4.w);
        *(float2*)&sm.g.Ws[r][kq * 4]     = make_float2(wv4.x, wv4.y);
        *(float2*)&sm.g.Ws[r][kq * 4 + 2] = make_float2(wv4.z, wv4.w);
    }
    __syncthreads();

    // ================= Phase 1: [G;H] = [s;t] @ W[:C]^T =====================
    // 512 threads, per-thread 2 rows x 4 cols, f32x2 FMA over k pairs.
    unsigned long long acc[8];
    {
        const int tx = tid & 15;          // col sub-index (stride 16)
        const int ty = tid >> 4;          // row 0..31 (rows ty, ty+32)
#pragma unroll
        for (int i = 0; i < 8; ++i) acc[i] = 0ull;

#pragma unroll 4
        for (int kk = 0; kk < 64; kk += 2) {
            unsigned long long xv0, xv1, wv[4];
            xv0 = *(const unsigned long long*)&sm.g.Xs[ty][kk];
            xv1 = *(const unsigned long long*)&sm.g.Xs[ty + 32][kk];
#pragma unroll
            for (int u = 0; u < 4; ++u)
                wv[u] = *(const unsigned long long*)&sm.g.Ws[tx + 16 * u][kk];
#pragma unroll
            for (int u = 0; u < 4; ++u) {
                asm("fma.rn.f32x2 %0, %1, %2, %0;" : "+l"(acc[u])     : "l"(xv0), "l"(wv[u]));
                asm("fma.rn.f32x2 %0, %1, %2, %0;" : "+l"(acc[4 + u]) : "l"(xv1), "l"(wv[u]));
            }
        }
    }
    __syncthreads();   // all warps done reading Xs/Ws; union reusable

    // ---- Pre-barrier: class-k broadcast + list building (ts/tt only) ----
    if (tid == bid) sh_k = my_tt;          // bid < 128 <= NT
    if (tid == 0) sh_last = 0;
    __syncthreads();
    const int k = sh_k;
    {
        const bool valid = tid < Nn;       // warps 0-3 only carry data
        const bool pM = valid && (my_ts == k);
        const bool pT = valid && (my_tt == k);
        const unsigned mM = __ballot_sync(0xffffffffu, pM);
        const unsigned mT = __ballot_sync(0xffffffffu, pT);
        if (lane == 0 && warp < 4) { sm.b.wM[warp] = __popc(mM); sm.b.wT[warp] = __popc(mT); }
        __syncthreads();
        const unsigned lt = (1u << lane) - 1u;
        if (warp < 4) {
            int bM = 0, bT = 0;
#pragma unroll
            for (int w = 0; w < 4; ++w)
                if (w < warp) { bM += sm.b.wM[w]; bT += sm.b.wT[w]; }
            if (pM) sm.b.mlist[bM + __popc(mM & lt)] = tid;
            if (pT) sm.b.tlist[bT + __popc(mT & lt)] = tid;
        }
    }
    const int cnt = sm.b.wM[0] + sm.b.wM[1] + sm.b.wM[2] + sm.b.wM[3];
    const int tnt = sm.b.wT[0] + sm.b.wT[1] + sm.b.wT[2] + sm.b.wT[3];

    // ---- GEMM epilogue: plain stores to this kt's private partial buffer ----
    {
        const int tx = tid & 15;
        const int ty = tid >> 4;
        float* base = g_part + (size_t)kt * (2 * Nn * Cc);
#pragma unroll
        for (int i = 0; i < 2; ++i)
#pragma unroll
            for (int u = 0; u < 4; ++u) {
                const unsigned long long a = acc[i * 4 + u];
                const float lo = __uint_as_float((unsigned int)(a & 0xffffffffull));
                const float hi = __uint_as_float((unsigned int)(a >> 32));
                base[(size_t)(m0 + ty + 32 * i) * Cc + c0 + tx + 16 * u] = lo + hi;
            }
    }

    // ================= Tree grid barrier (thread-0-only fences) =============
    __syncthreads();                     // HB: all threads' stores -> t0 fence
    if (tid == 0) {
        __threadfence();                 // release this block's stores
        const int grp = bid >> 3;
        const unsigned int gen = *(volatile unsigned int*)&g_genA;
        if (atomicAdd(&g_l1A[grp * 32], 1u) == 7u) {
            g_l1A[grp * 32] = 0u;
            __threadfence();             // order l1 chain before l2 RMW
            if (atomicAdd(&g_l2A, 1u) == 15u) {
                g_l2A = 0u;
                __threadfence();
                atomicAdd(&g_genA, 1u);
            } else {
                while (*(volatile unsigned int*)&g_genA == gen) { }
            }
        } else {
            while (*(volatile unsigned int*)&g_genA == gen) { }
        }
        __threadfence();                 // acquire
    }
    __syncthreads();                     // broadcast acquire to block

    // ===== Phase 2: class stats + sigma + softmax (split across halves) =====
    {
        const int n = bid;
        const int c = tid & 255;
        const int half = tid >> 8;       // 0 or 1

        if (tid < cnt) sm.b.pk[tid] = sum8(sm.b.mlist[tid], k);
        __syncthreads();

        const float invS = (cnt > 0) ? 1.0f / (float)cnt : 0.0f;  // w_cv zeroing
        const float invT = 1.0f / (float)tnt;                     // tnt >= 1 (n itself)

        float sumG = 0.f, s1 = 0.f, s2 = 0.f, sumH = 0.f;
        for (int j = half; j < cnt; j += 2) {
            const float gv = sum8(sm.b.mlist[j], c);
            const float a = gv - sm.b.pk[j];
            sumG += gv; s1 += a; s2 += a * a;
        }
        for (int j = half; j < tnt; j += 2)
            sumH += sum8(Nn + sm.b.tlist[j], c);

        if (half == 1) {
            sm.b.pG[c] = sumG; sm.b.pS1[c] = s1; sm.b.pS2[c] = s2; sm.b.pH[c] = sumH;
        }
        __syncthreads();

        float y = 0.f;
        if (half == 0) {
            sumG += sm.b.pG[c]; s1 += sm.b.pS1[c]; s2 += sm.b.pS2[c]; sumH += sm.b.pH[c];
            float sumpk = 0.f;
            for (int j = 0; j < cnt; ++j) sumpk += sm.b.pk[j];
            const float dbar  = invS * (sumG - sumpk);   // Gbar[c] - Gbar[k]
            const float sigma = invS * (s2 - 2.0f * dbar * s1 + (float)cnt * dbar * dbar);
            y = 0.5f * (sumG * invS + sumH * invT) + bias[c] + 0.25f * sigma;
        }

        // block max over the 256 valid y's (warps 0-7)
        float mmax = (half == 0) ? y : -3.4e38f;
#pragma unroll
        for (int o = 16; o; o >>= 1) mmax = fmaxf(mmax, __shfl_xor_sync(0xffffffffu, mmax, o));
        if (lane == 0 && warp < 8) sm.b.red[warp] = mmax;
        __syncthreads();
        mmax = sm.b.red[0];
#pragma unroll
        for (int w = 1; w < 8; ++w) mmax = fmaxf(mmax, sm.b.red[w]);
        __syncthreads();

        float e = (half == 0) ? expf(y - mmax) : 0.f;
#pragma unroll
        for (int o = 16; o; o >>= 1) e += __shfl_xor_sync(0xffffffffu, e, o);
        if (lane == 0 && warp < 8) sm.b.red[warp] = e;
        if (tid == k) sm.b.yk = y;       // k < 256, half 0 ✓
        __syncthreads();
        if (tid == 0) {
            float tot = 0.f;
#pragma unroll
            for (int w = 0; w < 8; ++w) tot += sm.b.red[w];
            g_loss[n] = -(sm.b.yk - mmax - logf(tot));   // plain store
        }
    }

    // ===== Completion tree: final-arriving block reduces the mean ===========
    if (tid == 0) {
        __threadfence();                 // publish g_loss[n] (stored by t0)
        const int grp = bid >> 3;
        if (atomicAdd(&g_l1B[grp * 32], 1u) == 7u) {
            g_l1B[grp * 32] = 0u;
            __threadfence();             // order l1 chain before l2 RMW
            if (atomicAdd(&g_l2B, 1u) == 15u) {
                g_l2B = 0u;
                sh_last = 1;
                __threadfence();         // acquire all g_loss stores
            }
        }
    }
    __syncthreads();
    if (sh_last) {
        float v = (tid < Nn) ? g_loss[tid] : 0.0f;
#pragma unroll
        for (int o = 16; o; o >>= 1) v += __shfl_xor_sync(0xffffffffu, v, o);
        if (lane == 0 && warp < 4) sm.b.red[warp] = v;
        __syncthreads();
        if (tid == 0) {
            float tot = sm.b.red[0] + sm.b.red[1] + sm.b.red[2] + sm.b.red[3];
            out[0] = tot * (1.0f / (float)Nn);
        }
    }
}

// ---------------------------------------------------------------------------
extern "C" void kernel_launch(void* const* d_in, const int* in_sizes, int n_in,
                              void* d_out, int out_size) {
    const float* fc_weight = (const float*)d_in[0];   // (2C, A)
    const float* fc_bias   = (const float*)d_in[1];   // (2C,)
    const float* s_feat    = (const float*)d_in[2];   // (N, A)
    const float* t_feat    = (const float*)d_in[3];   // (N, A)
    const int*   target_s  = (const int*)d_in[4];     // (N,)
    const int*   target_t  = (const int*)d_in[5];     // (N,)
    float* out = (float*)d_out;

    isda_fused_kernel<<<NB, NT>>>(fc_weight, fc_bias, s_feat, t_feat,
                                  target_s, target_t, out);
}

// round 11
// speedup vs baseline: 1.1562x; 1.1562x over previous
#include <cuda_runtime.h>
#include <math.h>

#define Nn 128
#define Cc 256
#define Aa 512
#define NB 128
#define NT 256
#define KSPLIT 8
#define TS 66              // smem row stride (floats): even (8B-aligned rows)

// Scratch (device globals — no allocations allowed). Counters are used once
// per run and reset by their last arriver; g_genA is monotonic (never reset).
__device__ float g_part[KSPLIT * 2 * Nn * Cc]; // K-split partials of [G;H]
__device__ unsigned int g_l1A[16 * 32];        // tree barrier level-1 (128B apart)
__device__ unsigned int g_l2A;
__device__ unsigned int g_genA;

struct SmemG { float Xs[64][TS]; float Ws[64][TS]; };
struct SmemB {
    int mlist[Nn], tlist[Nn];
    float pk[Nn];
    float red[8];
    float yk;
    int wM[4], wT[4];
};
union __align__(16) SmemU { SmemG g; SmemB b; };

// Sum the 8 K-split partials for element [row, col] of [G;H].
__device__ __forceinline__ float sum8(int row, int col) {
    float v = 0.f;
#pragma unroll
    for (int q = 0; q < KSPLIT; ++q)
        v += g_part[q * (2 * Nn * Cc) + row * Cc + col];
    return v;
}

__global__ __launch_bounds__(NT, 1)
void isda_fused_kernel(const float* __restrict__ W,
                       const float* __restrict__ bias,
                       const float* __restrict__ s,
                       const float* __restrict__ t,
                       const int* __restrict__ ts,
                       const int* __restrict__ tt,
                       float* __restrict__ out)
{
    __shared__ SmemU sm;
    __shared__ int sh_k;
    const int tid  = threadIdx.x;
    const int bid  = blockIdx.x;
    const int lane = tid & 31;
    const int warp = tid >> 5;

    // GEMM tile coordinates: 16 output tiles (64x64) x 8-way K-split
    const int mt = bid & 3;
    const int ct = (bid >> 2) & 3;
    const int kt = bid >> 4;
    const int m0 = mt * 64, c0 = ct * 64, kb = kt * 64;

    // ---- Cycle-0 loads: raw inputs, no dependencies ----
    const float* xbase = (mt < 2) ? (s + (size_t)m0 * Aa)
                                  : (t + (size_t)(m0 - 128) * Aa);
    int my_ts = 0, my_tt = 0;
    if (tid < Nn) { my_ts = ts[tid]; my_tt = tt[tid]; }
#pragma unroll
    for (int i = 0; i < 4; ++i) {
        const int idx = tid + i * 256;            // 0..1023
        const int r = idx >> 4, kq = idx & 15;
        const float4 xv4 = *(const float4*)&xbase[(size_t)r * Aa + kb + kq * 4];
        const float4 wv4 = *(const float4*)&W[(size_t)(c0 + r) * Aa + kb + kq * 4];
        *(float2*)&sm.g.Xs[r][kq * 4]     = make_float2(xv4.x, xv4.y);
        *(float2*)&sm.g.Xs[r][kq * 4 + 2] = make_float2(xv4.z, xv4.w);
        *(float2*)&sm.g.Ws[r][kq * 4]     = make_float2(wv4.x, wv4.y);
        *(float2*)&sm.g.Ws[r][kq * 4 + 2] = make_float2(wv4.z, wv4.w);
    }
    __syncthreads();

    // ================= Phase 1: [G;H] = [s;t] @ W[:C]^T =====================
    // 256 threads, per-thread 4 rows x 4 cols, f32x2 FMA over k pairs.
    unsigned long long acc[16];
    {
        const int tx = tid & 15;          // col sub-index (stride 16)
        const int ty = tid >> 4;          // row sub-index (stride 16)
#pragma unroll
        for (int i = 0; i < 16; ++i) acc[i] = 0ull;

#pragma unroll 4
        for (int kk = 0; kk < 64; kk += 2) {
            unsigned long long xv[4], wv[4];
#pragma unroll
            for (int i = 0; i < 4; ++i)
                xv[i] = *(const unsigned long long*)&sm.g.Xs[ty + 16 * i][kk];
#pragma unroll
            for (int u = 0; u < 4; ++u)
                wv[u] = *(const unsigned long long*)&sm.g.Ws[tx + 16 * u][kk];
#pragma unroll
            for (int i = 0; i < 4; ++i)
#pragma unroll
                for (int u = 0; u < 4; ++u)
                    asm("fma.rn.f32x2 %0, %1, %2, %0;"
                        : "+l"(acc[i * 4 + u]) : "l"(xv[i]), "l"(wv[u]));
        }
    }
    __syncthreads();   // all warps done reading Xs/Ws; union reusable

    // ---- Pre-barrier (overlaps barrier wait): lists from ts/tt only ----
    if (tid == bid) sh_k = my_tt;          // bid < 128 <= NT
    __syncthreads();
    const int k = sh_k;
    {
        const bool valid = tid < Nn;
        const bool pM = valid && (my_ts == k);
        const bool pT = valid && (my_tt == k);
        const unsigned mM = __ballot_sync(0xffffffffu, pM);
        const unsigned mT = __ballot_sync(0xffffffffu, pT);
        if (lane == 0 && warp < 4) { sm.b.wM[warp] = __popc(mM); sm.b.wT[warp] = __popc(mT); }
        __syncthreads();
        const unsigned lt = (1u << lane) - 1u;
        if (warp < 4) {
            int bM = 0, bT = 0;
#pragma unroll
            for (int w = 0; w < 4; ++w)
                if (w < warp) { bM += sm.b.wM[w]; bT += sm.b.wT[w]; }
            if (pM) sm.b.mlist[bM + __popc(mM & lt)] = tid;
            if (pT) sm.b.tlist[bT + __popc(mT & lt)] = tid;
        }
    }
    const int cnt = sm.b.wM[0] + sm.b.wM[1] + sm.b.wM[2] + sm.b.wM[3];
    const int tnt = sm.b.wT[0] + sm.b.wT[1] + sm.b.wT[2] + sm.b.wT[3];

    // ---- GEMM epilogue: plain stores to this kt's private partial buffer ----
    {
        const int tx = tid & 15;
        const int ty = tid >> 4;
        float* base = g_part + (size_t)kt * (2 * Nn * Cc);
#pragma unroll
        for (int i = 0; i < 4; ++i)
#pragma unroll
            for (int u = 0; u < 4; ++u) {
                const unsigned long long a = acc[i * 4 + u];
                const float lo = __uint_as_float((unsigned int)(a & 0xffffffffull));
                const float hi = __uint_as_float((unsigned int)(a >> 32));
                base[(size_t)(m0 + ty + 16 * i) * Cc + c0 + tx + 16 * u] = lo + hi;
            }
    }

    // ---- Zero the output before the barrier (ordered before all atomicAdds)
    if (bid == 0 && tid == 0) out[0] = 0.0f;

    // ================= Tree grid barrier (thread-0-only fences) =============
    __syncthreads();                     // HB: all threads' stores -> t0 fence
    if (tid == 0) {
        __threadfence();                 // release this block's stores
        const int grp = bid >> 3;
        const unsigned int gen = *(volatile unsigned int*)&g_genA;
        if (atomicAdd(&g_l1A[grp * 32], 1u) == 7u) {
            g_l1A[grp * 32] = 0u;
            __threadfence();             // order l1 chain before l2 RMW
            if (atomicAdd(&g_l2A, 1u) == 15u) {
                g_l2A = 0u;
                __threadfence();
                atomicAdd(&g_genA, 1u);
            } else {
                while (*(volatile unsigned int*)&g_genA == gen) { }
            }
        } else {
            while (*(volatile unsigned int*)&g_genA == gen) { }
        }
        __threadfence();                 // acquire
    }
    __syncthreads();                     // broadcast acquire to block

    // ===== Phase 2: class stats + sigma + softmax + direct atomic tail ======
    {
        const int c = tid;
        if (tid < cnt) sm.b.pk[tid] = sum8(sm.b.mlist[tid], k);
        __syncthreads();

        const float invS = (cnt > 0) ? 1.0f / (float)cnt : 0.0f;  // w_cv zeroing
        const float invT = 1.0f / (float)tnt;                     // tnt >= 1 (n itself)

        // Single pass: sums for mean + expanded-square sigma moments
        float sumpk = 0.f;
        for (int j = 0; j < cnt; ++j) sumpk += sm.b.pk[j];
        float sumG = 0.f, s1 = 0.f, s2 = 0.f;
#pragma unroll 2
        for (int j = 0; j < cnt; ++j) {
            const float gv = sum8(sm.b.mlist[j], c);
            const float a = gv - sm.b.pk[j];
            sumG += gv; s1 += a; s2 += a * a;
        }
        float sumH = 0.f;
#pragma unroll 2
        for (int j = 0; j < tnt; ++j)
            sumH += sum8(Nn + sm.b.tlist[j], c);

        const float dbar  = invS * (sumG - sumpk);   // Gbar[c] - Gbar[k]
        const float sigma = invS * (s2 - 2.0f * dbar * s1 + (float)cnt * dbar * dbar);
        float y = 0.5f * (sumG * invS + sumH * invT) + bias[c] + 0.25f * sigma;

        // block max
        float mmax = y;
#pragma unroll
        for (int o = 16; o; o >>= 1) mmax = fmaxf(mmax, __shfl_xor_sync(0xffffffffu, mmax, o));
        if (lane == 0) sm.b.red[warp] = mmax;
        __syncthreads();
        mmax = sm.b.red[0];
#pragma unroll
        for (int w = 1; w < 8; ++w) mmax = fmaxf(mmax, sm.b.red[w]);
        __syncthreads();

        float e = expf(y - mmax);
#pragma unroll
        for (int o = 16; o; o >>= 1) e += __shfl_xor_sync(0xffffffffu, e, o);
        if (lane == 0) sm.b.red[warp] = e;
        if (tid == k) sm.b.yk = y;
        __syncthreads();
        if (tid == 0) {
            float tot = 0.f;
#pragma unroll
            for (int w = 0; w < 8; ++w) tot += sm.b.red[w];
            const float loss_n = -(sm.b.yk - mmax - logf(tot));
            atomicAdd(out, loss_n * (1.0f / (float)Nn));   // fire-and-forget tail
        }
    }
}

// ---------------------------------------------------------------------------
extern "C" void kernel_launch(void* const* d_in, const int* in_sizes, int n_in,
                              void* d_out, int out_size) {
    const float* fc_weight = (const float*)d_in[0];   // (2C, A)
    const float* fc_bias   = (const float*)d_in[1];   // (2C,)
    const float* s_feat    = (const float*)d_in[2];   // (N, A)
    const float* t_feat    = (const float*)d_in[3];   // (N, A)
    const int*   target_s  = (const int*)d_in[4];     // (N,)
    const int*   target_t  = (const int*)d_in[5];     // (N,)
    float* out = (float*)d_out;

    isda_fused_kernel<<<NB, NT>>>(fc_weight, fc_bias, s_feat, t_feat,
                                  target_s, target_t, out);
}

// round 12
// speedup vs baseline: 1.3351x; 1.1546x over previous
#include <cuda_runtime.h>
#include <math.h>

#define Nn 128
#define Cc 256
#define Aa 512
#define NB 128
#define NT 256
#define KSPLIT 8
#define TS 66              // smem row stride (floats): even (8B-aligned rows)

// Scratch (device globals — no allocations allowed).
__device__ float g_part[KSPLIT * 2 * Nn * Cc]; // K-split partials of [G;H]

// ===========================================================================
// K1: [G;H] = [s;t] @ W[:C]^T  — 16 output tiles (64x64) x 8-way K-split.
// Also zeroes out[0] (ordered before K2's atomics by the kernel boundary).
// ===========================================================================
__global__ __launch_bounds__(NT, 1)
void isda_gemm_kernel(const float* __restrict__ W,
                      const float* __restrict__ s,
                      const float* __restrict__ t,
                      float* __restrict__ out)
{
    __shared__ float Xs[64][TS];
    __shared__ float Ws[64][TS];
    const int tid = threadIdx.x;
    const int bid = blockIdx.x;

    const int mt = bid & 3;
    const int ct = (bid >> 2) & 3;
    const int kt = bid >> 4;
    const int m0 = mt * 64, c0 = ct * 64, kb = kt * 64;

    if (bid == 0 && tid == 0) out[0] = 0.0f;

    const float* xbase = (mt < 2) ? (s + (size_t)m0 * Aa)
                                  : (t + (size_t)(m0 - 128) * Aa);
#pragma unroll
    for (int i = 0; i < 4; ++i) {
        const int idx = tid + i * 256;            // 0..1023
        const int r = idx >> 4, kq = idx & 15;
        const float4 xv4 = *(const float4*)&xbase[(size_t)r * Aa + kb + kq * 4];
        const float4 wv4 = *(const float4*)&W[(size_t)(c0 + r) * Aa + kb + kq * 4];
        *(float2*)&Xs[r][kq * 4]     = make_float2(xv4.x, xv4.y);
        *(float2*)&Xs[r][kq * 4 + 2] = make_float2(xv4.z, xv4.w);
        *(float2*)&Ws[r][kq * 4]     = make_float2(wv4.x, wv4.y);
        *(float2*)&Ws[r][kq * 4 + 2] = make_float2(wv4.z, wv4.w);
    }
    __syncthreads();

    const int tx = tid & 15;          // col sub-index (stride 16)
    const int ty = tid >> 4;          // row sub-index (stride 16)
    unsigned long long acc[16];
#pragma unroll
    for (int i = 0; i < 16; ++i) acc[i] = 0ull;

#pragma unroll 4
    for (int kk = 0; kk < 64; kk += 2) {
        unsigned long long xv[4], wv[4];
#pragma unroll
        for (int i = 0; i < 4; ++i)
            xv[i] = *(const unsigned long long*)&Xs[ty + 16 * i][kk];
#pragma unroll
        for (int u = 0; u < 4; ++u)
            wv[u] = *(const unsigned long long*)&Ws[tx + 16 * u][kk];
#pragma unroll
        for (int i = 0; i < 4; ++i)
#pragma unroll
            for (int u = 0; u < 4; ++u)
                asm("fma.rn.f32x2 %0, %1, %2, %0;"
                    : "+l"(acc[i * 4 + u]) : "l"(xv[i]), "l"(wv[u]));
    }

    float* base = g_part + (size_t)kt * (2 * Nn * Cc);
#pragma unroll
    for (int i = 0; i < 4; ++i)
#pragma unroll
        for (int u = 0; u < 4; ++u) {
            const unsigned long long a = acc[i * 4 + u];
            const float lo = __uint_as_float((unsigned int)(a & 0xffffffffull));
            const float hi = __uint_as_float((unsigned int)(a >> 32));
            base[(size_t)(m0 + ty + 16 * i) * Cc + c0 + tx + 16 * u] = lo + hi;
        }
}

// ===========================================================================
// K2: per-sample class stats + sigma + log-softmax + NLL; atomic mean tail.
// ===========================================================================
__device__ __forceinline__ float sum8(int row, int col) {
    float v = 0.f;
#pragma unroll
    for (int q = 0; q < KSPLIT; ++q)
        v += g_part[q * (2 * Nn * Cc) + row * Cc + col];
    return v;
}

__global__ __launch_bounds__(NT, 1)
void isda_loss_kernel(const float* __restrict__ bias,
                      const int* __restrict__ ts,
                      const int* __restrict__ tt,
                      float* __restrict__ out)
{
    __shared__ int mlist[Nn], tlist[Nn];
    __shared__ float pk[Nn];
    __shared__ float red[8];
    __shared__ float sh_yk;
    __shared__ int wM[4], wT[4];

    const int tid  = threadIdx.x;
    const int n    = blockIdx.x;
    const int lane = tid & 31;
    const int warp = tid >> 5;

    int my_ts = 0, my_tt = 0;
    if (tid < Nn) { my_ts = ts[tid]; my_tt = tt[tid]; }
    const int k = tt[n];

    {
        const bool valid = tid < Nn;
        const bool pM = valid && (my_ts == k);
        const bool pT = valid && (my_tt == k);
        const unsigned mM = __ballot_sync(0xffffffffu, pM);
        const unsigned mT = __ballot_sync(0xffffffffu, pT);
        if (lane == 0 && warp < 4) { wM[warp] = __popc(mM); wT[warp] = __popc(mT); }
        __syncthreads();
        const unsigned lt = (1u << lane) - 1u;
        if (warp < 4) {
            int bM = 0, bT = 0;
#pragma unroll
            for (int w = 0; w < 4; ++w)
                if (w < warp) { bM += wM[w]; bT += wT[w]; }
            if (pM) mlist[bM + __popc(mM & lt)] = tid;
            if (pT) tlist[bT + __popc(mT & lt)] = tid;
        }
    }
    const int cnt = wM[0] + wM[1] + wM[2] + wM[3];
    const int tnt = wT[0] + wT[1] + wT[2] + wT[3];
    __syncthreads();
    if (tid < cnt) pk[tid] = sum8(mlist[tid], k);
    __syncthreads();

    const float invS = (cnt > 0) ? 1.0f / (float)cnt : 0.0f;  // w_cv zeroing
    const float invT = 1.0f / (float)tnt;                     // tnt >= 1 (n itself)
    const int c = tid;

    // Single pass: sums for mean + expanded-square sigma moments
    float sumpk = 0.f;
    for (int j = 0; j < cnt; ++j) sumpk += pk[j];
    float sumG = 0.f, s1 = 0.f, s2 = 0.f;
#pragma unroll 2
    for (int j = 0; j < cnt; ++j) {
        const float gv = sum8(mlist[j], c);
        const float a = gv - pk[j];
        sumG += gv; s1 += a; s2 += a * a;
    }
    float sumH = 0.f;
#pragma unroll 2
    for (int j = 0; j < tnt; ++j)
        sumH += sum8(Nn + tlist[j], c);

    const float dbar  = invS * (sumG - sumpk);   // Gbar[c] - Gbar[k]
    const float sigma = invS * (s2 - 2.0f * dbar * s1 + (float)cnt * dbar * dbar);
    float y = 0.5f * (sumG * invS + sumH * invT) + bias[c] + 0.25f * sigma;

    // block max
    float mmax = y;
#pragma unroll
    for (int o = 16; o; o >>= 1) mmax = fmaxf(mmax, __shfl_xor_sync(0xffffffffu, mmax, o));
    if (lane == 0) red[warp] = mmax;
    __syncthreads();
    mmax = red[0];
#pragma unroll
    for (int w = 1; w < 8; ++w) mmax = fmaxf(mmax, red[w]);
    __syncthreads();

    float e = __expf(y - mmax);
#pragma unroll
    for (int o = 16; o; o >>= 1) e += __shfl_xor_sync(0xffffffffu, e, o);
    if (lane == 0) red[warp] = e;
    if (tid == k) sh_yk = y;
    __syncthreads();
    if (tid == 0) {
        float tot = 0.f;
#pragma unroll
        for (int w = 0; w < 8; ++w) tot += red[w];
        const float loss_n = -(sh_yk - mmax - __logf(tot));
        atomicAdd(out, loss_n * (1.0f / (float)Nn));
    }
}

// ---------------------------------------------------------------------------
extern "C" void kernel_launch(void* const* d_in, const int* in_sizes, int n_in,
                              void* d_out, int out_size) {
    const float* fc_weight = (const float*)d_in[0];   // (2C, A)
    const float* fc_bias   = (const float*)d_in[1];   // (2C,)
    const float* s_feat    = (const float*)d_in[2];   // (N, A)
    const float* t_feat    = (const float*)d_in[3];   // (N, A)
    const int*   target_s  = (const int*)d_in[4];     // (N,)
    const int*   target_t  = (const int*)d_in[5];     // (N,)
    float* out = (float*)d_out;

    isda_gemm_kernel<<<NB, NT>>>(fc_weight, s_feat, t_feat, out);
    isda_loss_kernel<<<NB, NT>>>(fc_bias, target_s, target_t, out);
}

// round 13
// speedup vs baseline: 1.3632x; 1.0211x over previous
#include <cuda_runtime.h>
#include <math.h>

#define Nn 128
#define Cc 256
#define Aa 512
#define NB 128
#define NT 256
#define KSPLIT 8
#define TS 66              // smem row stride (floats): even (8B-aligned rows)

// Scratch (device globals — no allocations allowed).
__device__ float g_part[KSPLIT * 2 * Nn * Cc]; // K-split partials of [G;H]

// ===========================================================================
// K1: [G;H] = [s;t] @ W[:C]^T  — 16 output tiles (64x64) x 8-way K-split.
// Fires the PDL trigger right after staging so K2's prologue overlaps compute.
// Also zeroes out[0] (K2 only adds to it after gridDependencySynchronize).
// ===========================================================================
__global__ __launch_bounds__(NT, 1)
void isda_gemm_kernel(const float* __restrict__ W,
                      const float* __restrict__ s,
                      const float* __restrict__ t,
                      float* __restrict__ out)
{
    __shared__ float Xs[64][TS];
    __shared__ float Ws[64][TS];
    const int tid = threadIdx.x;
    const int bid = blockIdx.x;

    const int mt = bid & 3;
    const int ct = (bid >> 2) & 3;
    const int kt = bid >> 4;
    const int m0 = mt * 64, c0 = ct * 64, kb = kt * 64;

    if (bid == 0 && tid == 0) out[0] = 0.0f;

    const float* xbase = (mt < 2) ? (s + (size_t)m0 * Aa)
                                  : (t + (size_t)(m0 - 128) * Aa);
#pragma unroll
    for (int i = 0; i < 4; ++i) {
        const int idx = tid + i * 256;            // 0..1023
        const int r = idx >> 4, kq = idx & 15;
        const float4 xv4 = *(const float4*)&xbase[(size_t)r * Aa + kb + kq * 4];
        const float4 wv4 = *(const float4*)&W[(size_t)(c0 + r) * Aa + kb + kq * 4];
        *(float2*)&Xs[r][kq * 4]     = make_float2(xv4.x, xv4.y);
        *(float2*)&Xs[r][kq * 4 + 2] = make_float2(xv4.z, xv4.w);
        *(float2*)&Ws[r][kq * 4]     = make_float2(wv4.x, wv4.y);
        *(float2*)&Ws[r][kq * 4 + 2] = make_float2(wv4.z, wv4.w);
    }
    __syncthreads();

    // Inputs consumed; let the dependent kernel's prologue start now.
    cudaTriggerProgrammaticLaunchCompletion();

    const int tx = tid & 15;          // col sub-index (stride 16)
    const int ty = tid >> 4;          // row sub-index (stride 16)
    unsigned long long acc[16];
#pragma unroll
    for (int i = 0; i < 16; ++i) acc[i] = 0ull;

#pragma unroll 4
    for (int kk = 0; kk < 64; kk += 2) {
        unsigned long long xv[4], wv[4];
#pragma unroll
        for (int i = 0; i < 4; ++i)
            xv[i] = *(const unsigned long long*)&Xs[ty + 16 * i][kk];
#pragma unroll
        for (int u = 0; u < 4; ++u)
            wv[u] = *(const unsigned long long*)&Ws[tx + 16 * u][kk];
#pragma unroll
        for (int i = 0; i < 4; ++i)
#pragma unroll
            for (int u = 0; u < 4; ++u)
                asm("fma.rn.f32x2 %0, %1, %2, %0;"
                    : "+l"(acc[i * 4 + u]) : "l"(xv[i]), "l"(wv[u]));
    }

    float* base = g_part + (size_t)kt * (2 * Nn * Cc);
#pragma unroll
    for (int i = 0; i < 4; ++i)
#pragma unroll
        for (int u = 0; u < 4; ++u) {
            const unsigned long long a = acc[i * 4 + u];
            const float lo = __uint_as_float((unsigned int)(a & 0xffffffffull));
            const float hi = __uint_as_float((unsigned int)(a >> 32));
            base[(size_t)(m0 + ty + 16 * i) * Cc + c0 + tx + 16 * u] = lo + hi;
        }
}

// ===========================================================================
// K2: prologue (lists, bias) overlaps K1 via PDL; gridDependencySynchronize
// before consuming g_part; sigma + log-softmax + NLL; atomic mean tail.
// ===========================================================================
__device__ __forceinline__ float sum8(int row, int col) {
    float v = 0.f;
#pragma unroll
    for (int q = 0; q < KSPLIT; ++q)
        v += g_part[q * (2 * Nn * Cc) + row * Cc + col];
    return v;
}

__global__ __launch_bounds__(NT, 1)
void isda_loss_kernel(const float* __restrict__ bias,
                      const int* __restrict__ ts,
                      const int* __restrict__ tt,
                      float* __restrict__ out)
{
    __shared__ int mlist[Nn], tlist[Nn];
    __shared__ float pk[Nn];
    __shared__ float red[8];
    __shared__ float sh_yk;
    __shared__ int wM[4], wT[4];

    const int tid  = threadIdx.x;
    const int n    = blockIdx.x;
    const int lane = tid & 31;
    const int warp = tid >> 5;

    // ---------------- Prologue: independent of K1's output ----------------
    int my_ts = 0, my_tt = 0;
    if (tid < Nn) { my_ts = ts[tid]; my_tt = tt[tid]; }
    const int k = tt[n];
    const float my_bias = bias[tid];

    {
        const bool valid = tid < Nn;
        const bool pM = valid && (my_ts == k);
        const bool pT = valid && (my_tt == k);
        const unsigned mM = __ballot_sync(0xffffffffu, pM);
        const unsigned mT = __ballot_sync(0xffffffffu, pT);
        if (lane == 0 && warp < 4) { wM[warp] = __popc(mM); wT[warp] = __popc(mT); }
        __syncthreads();
        const unsigned lt = (1u << lane) - 1u;
        if (warp < 4) {
            int bM = 0, bT = 0;
#pragma unroll
            for (int w = 0; w < 4; ++w)
                if (w < warp) { bM += wM[w]; bT += wT[w]; }
            if (pM) mlist[bM + __popc(mM & lt)] = tid;
            if (pT) tlist[bT + __popc(mT & lt)] = tid;
        }
    }
    const int cnt = wM[0] + wM[1] + wM[2] + wM[3];
    const int tnt = wT[0] + wT[1] + wT[2] + wT[3];
    __syncthreads();

    // ---------------- Wait for K1's g_part to be complete ------------------
    cudaGridDependencySynchronize();

    if (tid < cnt) pk[tid] = sum8(mlist[tid], k);
    __syncthreads();

    const float invS = (cnt > 0) ? 1.0f / (float)cnt : 0.0f;  // w_cv zeroing
    const float invT = 1.0f / (float)tnt;                     // tnt >= 1 (n itself)
    const int c = tid;

    // Single pass: sums for mean + expanded-square sigma moments
    float sumpk = 0.f;
    for (int j = 0; j < cnt; ++j) sumpk += pk[j];
    float sumG = 0.f, s1 = 0.f, s2 = 0.f;
#pragma unroll 2
    for (int j = 0; j < cnt; ++j) {
        const float gv = sum8(mlist[j], c);
        const float a = gv - pk[j];
        sumG += gv; s1 += a; s2 += a * a;
    }
    float sumH = 0.f;
#pragma unroll 2
    for (int j = 0; j < tnt; ++j)
        sumH += sum8(Nn + tlist[j], c);

    const float dbar  = invS * (sumG - sumpk);   // Gbar[c] - Gbar[k]
    const float sigma = invS * (s2 - 2.0f * dbar * s1 + (float)cnt * dbar * dbar);
    float y = 0.5f * (sumG * invS + sumH * invT) + my_bias + 0.25f * sigma;

    // block max
    float mmax = y;
#pragma unroll
    for (int o = 16; o; o >>= 1) mmax = fmaxf(mmax, __shfl_xor_sync(0xffffffffu, mmax, o));
    if (lane == 0) red[warp] = mmax;
    __syncthreads();
    mmax = red[0];
#pragma unroll
    for (int w = 1; w < 8; ++w) mmax = fmaxf(mmax, red[w]);
    __syncthreads();

    float e = __expf(y - mmax);
#pragma unroll
    for (int o = 16; o; o >>= 1) e += __shfl_xor_sync(0xffffffffu, e, o);
    if (lane == 0) red[warp] = e;
    if (tid == k) sh_yk = y;
    __syncthreads();
    if (tid == 0) {
        float tot = 0.f;
#pragma unroll
        for (int w = 0; w < 8; ++w) tot += red[w];
        const float loss_n = -(sh_yk - mmax - __logf(tot));
        atomicAdd(out, loss_n * (1.0f / (float)Nn));
    }
}

// ---------------------------------------------------------------------------
extern "C" void kernel_launch(void* const* d_in, const int* in_sizes, int n_in,
                              void* d_out, int out_size) {
    const float* fc_weight = (const float*)d_in[0];   // (2C, A)
    const float* fc_bias   = (const float*)d_in[1];   // (2C,)
    const float* s_feat    = (const float*)d_in[2];   // (N, A)
    const float* t_feat    = (const float*)d_in[3];   // (N, A)
    const int*   target_s  = (const int*)d_in[4];     // (N,)
    const int*   target_t  = (const int*)d_in[5];     // (N,)
    float* out = (float*)d_out;

    isda_gemm_kernel<<<NB, NT>>>(fc_weight, s_feat, t_feat, out);

    // K2 with Programmatic Dependent Launch: its prologue overlaps K1.
    cudaLaunchConfig_t cfg = {};
    cfg.gridDim  = dim3(NB, 1, 1);
    cfg.blockDim = dim3(NT, 1, 1);
    cfg.dynamicSmemBytes = 0;
    cfg.stream = 0;
    cudaLaunchAttribute attr[1];
    attr[0].id = cudaLaunchAttributeProgrammaticStreamSerialization;
    attr[0].val.programmaticStreamSerializationAllowed = 1;
    cfg.attrs = attr;
    cfg.numAttrs = 1;
    cudaLaunchKernelEx(&cfg, isda_loss_kernel, fc_bias, target_s, target_t,
                       (float*)d_out);
}